// round 4
// baseline (speedup 1.0000x reference)
#include <cuda_runtime.h>
#include <stdint.h>

#define ROW_BYTES 3072          // 768 floats
#define D 8                     // pipeline depth (stages)
#define TOKENS_PER_CTA 16

__device__ __forceinline__ uint32_t smem_u32(const void* p) {
    return (uint32_t)__cvta_generic_to_shared(p);
}

// One warp per CTA; lane 0 drives a depth-D cp.async.bulk pipeline:
//   load row (global->smem, mbarrier complete_tx)  then  store (smem->global, bulk_group).
// Buffer reuse is gated by cp.async.bulk.wait_group.read (SMEM reads done).
// Index dtype (int32 vs int64) detected from odd 32-bit words: int64 storage
// has all-zero high halves; 32 random int32 vocab ids all zero ~ (1/50257)^32.
__global__ void __launch_bounds__(32)
embedding_tma(const void* __restrict__ idx_raw,
              const char* __restrict__ table,
              char* __restrict__ out,
              int n_tokens) {
    __shared__ alignas(128) char buf[D][ROW_BYTES];
    __shared__ alignas(8) uint64_t mbar[D];

    // ---- dtype detection (whole warp, 256B coalesced, L2-hot) ----
    const unsigned int* w = (const unsigned int*)idx_raw;
    int widx = 2 * threadIdx.x + 1;
    unsigned int probe = (widx < n_tokens) ? w[widx] : 0u;
    bool idx_is_i32 = (__ballot_sync(0xFFFFFFFFu, probe != 0u) != 0u);

    if (threadIdx.x != 0) return;   // lane 0 does all the work

    int t0 = blockIdx.x * TOKENS_PER_CTA;
    int tend = t0 + TOKENS_PER_CTA;
    if (tend > n_tokens) tend = n_tokens;
    int T = tend - t0;
    if (T <= 0) return;

    #pragma unroll
    for (int s = 0; s < D; s++) {
        uint32_t mb = smem_u32(&mbar[s]);
        asm volatile("mbarrier.init.shared.b64 [%0], %1;" :: "r"(mb), "r"(1) : "memory");
    }
    asm volatile("fence.proxy.async.shared::cta;" ::: "memory");

    const int* idx32 = (const int*)idx_raw;
    const long long* idx64 = (const long long*)idx_raw;

    // ---- prologue: fill up to D stages ----
    int npro = (T < D) ? T : D;
    for (int s = 0; s < npro; s++) {
        long long idx = idx_is_i32 ? (long long)idx32[t0 + s] : idx64[t0 + s];
        uint32_t mb = smem_u32(&mbar[s]);
        asm volatile("mbarrier.arrive.expect_tx.shared::cta.b64 _, [%0], %1;"
                     :: "r"(mb), "r"(ROW_BYTES) : "memory");
        asm volatile("cp.async.bulk.shared::cta.global.mbarrier::complete_tx::bytes "
                     "[%0], [%1], %2, [%3];"
                     :: "r"(smem_u32(buf[s])), "l"(table + idx * (long long)ROW_BYTES),
                        "r"(ROW_BYTES), "r"(mb) : "memory");
    }

    // ---- main loop ----
    for (int j = 0; j < T; j++) {
        // refill the stage freed by LAST iteration's store (hides store-read latency)
        if (j > 0) {
            int nt = (j - 1) + D;            // token to load next
            if (nt < T) {
                // all committed store groups' SMEM reads must be done before reuse
                asm volatile("cp.async.bulk.wait_group.read 0;" ::: "memory");
                int s = (j - 1) % D;
                long long idx = idx_is_i32 ? (long long)idx32[t0 + nt] : idx64[t0 + nt];
                uint32_t mb = smem_u32(&mbar[s]);
                asm volatile("mbarrier.arrive.expect_tx.shared::cta.b64 _, [%0], %1;"
                             :: "r"(mb), "r"(ROW_BYTES) : "memory");
                asm volatile("cp.async.bulk.shared::cta.global.mbarrier::complete_tx::bytes "
                             "[%0], [%1], %2, [%3];"
                             :: "r"(smem_u32(buf[s])), "l"(table + idx * (long long)ROW_BYTES),
                                "r"(ROW_BYTES), "r"(mb) : "memory");
            }
        }

        int s = j % D;
        int phase = (j / D) & 1;
        uint32_t mb = smem_u32(&mbar[s]);
        // wait for load of token j
        uint32_t done;
        do {
            asm volatile("{\n\t.reg .pred p;\n\t"
                         "mbarrier.try_wait.parity.shared::cta.b64 p, [%1], %2, 10000000;\n\t"
                         "selp.b32 %0, 1, 0, p;\n\t}"
                         : "=r"(done) : "r"(mb), "r"(phase) : "memory");
        } while (!done);

        asm volatile("cp.async.bulk.global.shared::cta.bulk_group [%0], [%1], %2;"
                     :: "l"(out + (long long)(t0 + j) * ROW_BYTES),
                        "r"(smem_u32(buf[s])), "r"(ROW_BYTES) : "memory");
        asm volatile("cp.async.bulk.commit_group;" ::: "memory");
    }

    // drain stores before exit
    asm volatile("cp.async.bulk.wait_group 0;" ::: "memory");
}

extern "C" void kernel_launch(void* const* d_in, const int* in_sizes, int n_in,
                              void* d_out, int out_size) {
    // indices buffer is the small one; table is 50257*768 elements.
    const void* d_idx;
    const void* d_table;
    int n_tokens;
    if (in_sizes[0] < in_sizes[1]) {
        d_idx = d_in[0];  d_table = d_in[1];  n_tokens = in_sizes[0];
    } else {
        d_idx = d_in[1];  d_table = d_in[0];  n_tokens = in_sizes[1];
    }

    int blocks = (n_tokens + TOKENS_PER_CTA - 1) / TOKENS_PER_CTA;
    embedding_tma<<<blocks, 32>>>(d_idx,
                                  (const char*)d_table,
                                  (char*)d_out,
                                  n_tokens);
}